// round 13
// baseline (speedup 1.0000x reference)
#include <cuda_runtime.h>
#include <cuda_fp16.h>

#define Nn 50000
#define Ee 800000
#define NEG_SLOPE 0.2f
#define CAP 128            // ELL row capacity (real edges only; Poisson(17) in-degree)
#define H1 25024           // node split point (multiple of 64)
#define AGG_W 16           // warps per aggregate block

typedef unsigned int uint;
typedef unsigned long long u64;

// ---------------- scratch ----------------
__device__ uint   g_hh1[Nn * 64];    // layer-1 h as half2 units
__device__ uint   g_hh2[Nn * 64];    // layer-2 h as half2 units (double buffer)
__device__ uint   g_x2h[Nn * 32];    // layer-1 output as half2 units
__device__ float  g_asrc1[Nn * 2];
__device__ float  g_adst1[Nn * 2];
__device__ float  g_asrc2[Nn * 2];
__device__ float  g_adst2[Nn * 2];
__device__ int    g_cnt[Nn];         // INVARIANT: zero outside fill->agg2 window
__device__ int    g_ell[Nn * CAP];   // padded adjacency (real edges; self-loop implicit)
__device__ uint2  g_Bp1[8 * 512];    // layer-1 W fragments (K=128)
__device__ uint2  g_Bp2[4 * 512];    // layer-2 W fragments (K=64)

// ---------------- helpers ----------------
__device__ __forceinline__ uint packh2(float a, float b) {
    __half2 h = __floats2half2_rn(a, b);
    return *(uint*)&h;
}
__device__ __forceinline__ void mma16(float* c, const uint* a, uint b0, uint b1) {
    asm volatile(
        "mma.sync.aligned.m16n8k16.row.col.f32.f16.f16.f32 "
        "{%0,%1,%2,%3},{%4,%5,%6,%7},{%8,%9},{%0,%1,%2,%3};"
        : "+f"(c[0]), "+f"(c[1]), "+f"(c[2]), "+f"(c[3])
        : "r"(a[0]), "r"(a[1]), "r"(a[2]), "r"(a[3]), "r"(b0), "r"(b1));
}
__device__ __forceinline__ u64 packf2(float x, float y) {
    u64 u; asm("mov.b64 %0, {%1,%2};" : "=l"(u) : "f"(x), "f"(y)); return u;
}
__device__ __forceinline__ float2 unpackf2(u64 u) {
    float2 f; asm("mov.b64 {%0,%1}, %2;" : "=f"(f.x), "=f"(f.y) : "l"(u)); return f;
}
__device__ __forceinline__ void fma_f32x2(u64& acc, u64 h, u64 a) {
    asm("fma.rn.f32x2 %0, %1, %2, %0;" : "+l"(acc) : "l"(h), "l"(a));
}

// =================== ELL build (cnt starts at 0 by countdown invariant) ===================
__global__ void fill_kernel(const int* __restrict__ ei) {
    int i = blockIdx.x * blockDim.x + threadIdx.x;
    if (i >= Ee / 4) return;
    int4 s = ((const int4*)ei)[i];
    int4 d = ((const int4*)(ei + Ee))[i];
    int o;
    o = atomicAdd(&g_cnt[d.x], 1); if (o < CAP) g_ell[(d.x << 7) + o] = s.x;
    o = atomicAdd(&g_cnt[d.y], 1); if (o < CAP) g_ell[(d.y << 7) + o] = s.y;
    o = atomicAdd(&g_cnt[d.z], 1); if (o < CAP) g_ell[(d.z << 7) + o] = s.z;
    o = atomicAdd(&g_cnt[d.w], 1); if (o < CAP) g_ell[(d.w << 7) + o] = s.w;
}

// =================== merged B fragment prep (both layers) ===================
__device__ __forceinline__ void bfrag(const float* __restrict__ W, uint2* __restrict__ Bp, int e) {
    int ks   = e >> 9;
    int rem  = e & 511;
    int tp   = rem >> 5;
    int lane = rem & 31;
    int g = lane >> 2, t = lane & 3;
    int k0 = ks * 16 + 2 * t;
    int n  = tp * 8 + g;
    uint2 p;
    p.x = packh2(W[k0 * 128 + n],       W[(k0 + 1) * 128 + n]);
    p.y = packh2(W[(k0 + 8) * 128 + n], W[(k0 + 9) * 128 + n]);
    Bp[e] = p;
}
__global__ void bprep_all_kernel(const float* __restrict__ W1, const float* __restrict__ W2) {
    int e = blockIdx.x * blockDim.x + threadIdx.x;
    if (e < 8 * 512)       bfrag(W1, g_Bp1, e);
    else if (e < 12 * 512) bfrag(W2, g_Bp2, e - 8 * 512);
}

// =================== GEMM (fp16 HMMA, fp32 acc) + fused attention dots ===================
template <int K, bool HALF_IN>
__global__ void __launch_bounds__(128) gemm_att_kernel(const void* __restrict__ Xv,
                                                       const uint2* __restrict__ Bp,
                                                       const float* __restrict__ asv,
                                                       const float* __restrict__ adv,
                                                       uint* __restrict__ hhOut,
                                                       float* __restrict__ asrcOut,
                                                       float* __restrict__ adstOut,
                                                       int rowOff, int rowLim) {
    int w = threadIdx.x >> 5, lane = threadIdx.x & 31;
    int g = lane >> 2, t = lane & 3;
    int rowb = rowOff + blockIdx.x * 64 + w * 16;
    int r0 = rowb + g, r1 = r0 + 8;
    bool p0 = r0 < rowLim, p1 = r1 < rowLim;
    const float* Xf = (const float*)Xv;
    const uint*  Xh = (const uint*)Xv;

    float acc[16][4] = {};
#pragma unroll
    for (int ks = 0; ks < K / 16; ks++) {
        int kA = ks * 16 + 2 * t;
        uint a[4];
        if (HALF_IN) {
            a[0] = p0 ? Xh[(r0 * K + kA) >> 1]     : 0u;
            a[1] = p1 ? Xh[(r1 * K + kA) >> 1]     : 0u;
            a[2] = p0 ? Xh[(r0 * K + kA + 8) >> 1] : 0u;
            a[3] = p1 ? Xh[(r1 * K + kA + 8) >> 1] : 0u;
        } else {
            float2 f0 = p0 ? *(const float2*)&Xf[r0 * K + kA]     : make_float2(0.f, 0.f);
            float2 f1 = p1 ? *(const float2*)&Xf[r1 * K + kA]     : make_float2(0.f, 0.f);
            float2 f2 = p0 ? *(const float2*)&Xf[r0 * K + kA + 8] : make_float2(0.f, 0.f);
            float2 f3 = p1 ? *(const float2*)&Xf[r1 * K + kA + 8] : make_float2(0.f, 0.f);
            a[0] = packh2(f0.x, f0.y);
            a[1] = packh2(f1.x, f1.y);
            a[2] = packh2(f2.x, f2.y);
            a[3] = packh2(f3.x, f3.y);
        }
        const uint2* bp = Bp + ks * 512 + lane;
#pragma unroll
        for (int tp = 0; tp < 16; tp++) {
            uint2 b = bp[tp * 32];
            mma16(acc[tp], a, b.x, b.y);
        }
    }

#pragma unroll
    for (int n = 0; n < 16; n++) {
        int c = n * 8 + 2 * t;
        if (p0) hhOut[(r0 * 128 + c) >> 1] = packh2(acc[n][0], acc[n][1]);
        if (p1) hhOut[(r1 * 128 + c) >> 1] = packh2(acc[n][2], acc[n][3]);
    }

    float sa[2][2] = {};
    float sd_[2][2] = {};
#pragma unroll
    for (int n = 0; n < 16; n++) {
        int c = n * 8 + 2 * t;
        float v0 = asv[c], v1 = asv[c + 1];
        float u0 = adv[c], u1 = adv[c + 1];
        int hh = n >> 3;
        sa[0][hh] += acc[n][0] * v0 + acc[n][1] * v1;
        sa[1][hh] += acc[n][2] * v0 + acc[n][3] * v1;
        sd_[0][hh] += acc[n][0] * u0 + acc[n][1] * u1;
        sd_[1][hh] += acc[n][2] * u0 + acc[n][3] * u1;
    }
#pragma unroll
    for (int rh = 0; rh < 2; rh++)
#pragma unroll
        for (int hh = 0; hh < 2; hh++) {
            sa[rh][hh] += __shfl_xor_sync(~0u, sa[rh][hh], 1);
            sa[rh][hh] += __shfl_xor_sync(~0u, sa[rh][hh], 2);
            sd_[rh][hh] += __shfl_xor_sync(~0u, sd_[rh][hh], 1);
            sd_[rh][hh] += __shfl_xor_sync(~0u, sd_[rh][hh], 2);
        }
    if (t == 0) {
        if (p0) {
            asrcOut[r0 * 2] = sa[0][0]; asrcOut[r0 * 2 + 1] = sa[0][1];
            adstOut[r0 * 2] = sd_[0][0]; adstOut[r0 * 2 + 1] = sd_[0][1];
        }
        if (p1) {
            asrcOut[r1 * 2] = sa[1][0]; asrcOut[r1 * 2 + 1] = sa[1][1];
            adstOut[r1 * 2] = sd_[1][0]; adstOut[r1 * 2 + 1] = sd_[1][1];
        }
    }
}

// =================== aggregate over node range [n0, n1) ===================
// float4 smem staging (1 LDS.128/edge); unnormalized accumulate; unroll 8.
template <bool FC, bool RESET>
__global__ void __launch_bounds__(AGG_W * 32) aggregate_kernel(
                                 const uint* __restrict__ hh,
                                 const float* __restrict__ asrc,
                                 const float* __restrict__ adst,
                                 const float* __restrict__ bias,
                                 const float* __restrict__ fcW,
                                 const float* __restrict__ fcb,
                                 float* __restrict__ out,
                                 int n0, int n1) {
    __shared__ float4 s_e[AGG_W][32];   // (src_as_float_bits, p0, p1, unused)
    int tid = threadIdx.x;
    int wiw = tid >> 5;
    int warp = n0 + ((blockIdx.x * blockDim.x + tid) >> 5);
    int lane = tid & 31;
    if (warp >= n1) return;
    int base = warp << 7;
    int cnt = min(g_cnt[warp], CAP);
    float2 ad = *(const float2*)&adst[warp * 2];
    bool lo = (lane < 16);

    // self-loop logit
    float2 aself = *(const float2*)&asrc[warp * 2];
    float se0 = aself.x + ad.x; se0 = se0 > 0.f ? se0 : NEG_SLOPE * se0;
    float se1 = aself.y + ad.y; se1 = se1 > 0.f ? se1 : NEG_SLOPE * se1;
    se0 = __expf(fminf(se0, 60.f));
    se1 = __expf(fminf(se1, 60.f));

    // pass 1: edge logits + exp + sum; first 32 edges staged to smem as float4
    float s0 = (lane == 0) ? se0 : 0.f;
    float s1 = (lane == 0) ? se1 : 0.f;
    if (lane < cnt) {
        int s = g_ell[base + lane];
        float2 as = *(const float2*)&asrc[s * 2];
        float e0 = as.x + ad.x; e0 = e0 > 0.f ? e0 : NEG_SLOPE * e0;
        float e1 = as.y + ad.y; e1 = e1 > 0.f ? e1 : NEG_SLOPE * e1;
        float fp0 = __expf(fminf(e0, 60.f));
        float fp1 = __expf(fminf(e1, 60.f));
        s_e[wiw][lane] = make_float4(__int_as_float(s), fp0, fp1, 0.f);
        s0 += fp0; s1 += fp1;
        for (int j = lane + 32; j < cnt; j += 32) {
            int s2 = g_ell[base + j];
            float2 a2 = *(const float2*)&asrc[s2 * 2];
            float q0 = a2.x + ad.x; q0 = q0 > 0.f ? q0 : NEG_SLOPE * q0;
            float q1 = a2.y + ad.y; q1 = q1 > 0.f ? q1 : NEG_SLOPE * q1;
            s0 += __expf(fminf(q0, 60.f));
            s1 += __expf(fminf(q1, 60.f));
        }
    }
    __syncwarp();
#pragma unroll
    for (int o = 16; o > 0; o >>= 1) {
        s0 += __shfl_xor_sync(~0u, s0, o);
        s1 += __shfl_xor_sync(~0u, s1, o);
    }
    float inv = lo ? 1.f / (s0 + 1e-16f) : 1.f / (s1 + 1e-16f);

    // pass 2: UNNORMALIZED weighted fp16 gather; self term first
    u64 acc01, acc23;
    {
        float a = lo ? se0 : se1;
        uint2 hu = *(const uint2*)&hh[warp * 64 + lane * 2];
        float2 f0 = __half22float2(*(__half2*)&hu.x);
        float2 f1 = __half22float2(*(__half2*)&hu.y);
        acc01 = packf2(a * f0.x, a * f0.y);
        acc23 = packf2(a * f1.x, a * f1.y);
    }
    const uint* hbase = hh + lane * 2;
    int cn = min(32, cnt);
#pragma unroll 8
    for (int j = 0; j < cn; j++) {
        float4 e = s_e[wiw][j];
        int   s = __float_as_int(e.x);
        float a = lo ? e.y : e.z;
        u64 aa = packf2(a, a);
        uint2 hu = *(const uint2*)&hbase[s * 64];
        float2 f0 = __half22float2(*(__half2*)&hu.x);
        float2 f1 = __half22float2(*(__half2*)&hu.y);
        fma_f32x2(acc01, packf2(f0.x, f0.y), aa);
        fma_f32x2(acc23, packf2(f1.x, f1.y), aa);
    }
    float2 a01 = unpackf2(acc01), a23 = unpackf2(acc23);
    float4 acc = make_float4(a01.x, a01.y, a23.x, a23.y);

    // cold path: degree > 32 — recompute exp, accumulate unnormalized
    for (int jb = 32; jb < cnt; jb += 32) {
        int idx = jb + lane;
        int   ls = 0;
        float lp0 = 0.f, lp1 = 0.f;
        if (idx < cnt) {
            ls = g_ell[base + idx];
            float2 a2 = *(const float2*)&asrc[ls * 2];
            float q0 = a2.x + ad.x; q0 = q0 > 0.f ? q0 : NEG_SLOPE * q0;
            float q1 = a2.y + ad.y; q1 = q1 > 0.f ? q1 : NEG_SLOPE * q1;
            lp0 = __expf(fminf(q0, 60.f));
            lp1 = __expf(fminf(q1, 60.f));
        }
        int n = min(32, cnt - jb);
        for (int j = 0; j < n; j++) {
            int   s  = __shfl_sync(~0u, ls, j);
            float q0 = __shfl_sync(~0u, lp0, j);
            float q1 = __shfl_sync(~0u, lp1, j);
            float a = lo ? q0 : q1;
            uint2 hu = *(const uint2*)&hbase[s * 64];
            float2 f0 = __half22float2(*(__half2*)&hu.x);
            float2 f1 = __half22float2(*(__half2*)&hu.y);
            acc.x += a * f0.x; acc.y += a * f0.y; acc.z += a * f1.x; acc.w += a * f1.y;
        }
    }

    // normalize, then head mean
    acc.x *= inv; acc.y *= inv; acc.z *= inv; acc.w *= inv;
    float4 o4;
    o4.x = (acc.x + __shfl_xor_sync(~0u, acc.x, 16)) * 0.5f;
    o4.y = (acc.y + __shfl_xor_sync(~0u, acc.y, 16)) * 0.5f;
    o4.z = (acc.z + __shfl_xor_sync(~0u, acc.z, 16)) * 0.5f;
    o4.w = (acc.w + __shfl_xor_sync(~0u, acc.w, 16)) * 0.5f;

    if (RESET) {
        if (lane == 0) g_cnt[warp] = 0;   // restore countdown invariant for next replay
    }

    if (!FC) {
        if (lane < 16) {
            float4 b4 = *(const float4*)&bias[lane * 4];
            o4.x = fmaxf(o4.x + b4.x, 0.f);
            o4.y = fmaxf(o4.y + b4.y, 0.f);
            o4.z = fmaxf(o4.z + b4.z, 0.f);
            o4.w = fmaxf(o4.w + b4.w, 0.f);
            uint2 p;
            p.x = packh2(o4.x, o4.y);
            p.y = packh2(o4.z, o4.w);
            *(uint2*)&((uint*)out)[warp * 32 + lane * 2] = p;
        }
    } else {
        float p = 0.f;
        if (lane < 16) {
            float4 b4 = *(const float4*)&bias[lane * 4];
            float4 w4 = *(const float4*)&fcW[lane * 4];
            p  = fmaxf(o4.x + b4.x, 0.f) * w4.x;
            p += fmaxf(o4.y + b4.y, 0.f) * w4.y;
            p += fmaxf(o4.z + b4.z, 0.f) * w4.z;
            p += fmaxf(o4.w + b4.w, 0.f) * w4.w;
        }
#pragma unroll
        for (int o = 8; o > 0; o >>= 1) p += __shfl_xor_sync(~0u, p, o);
        if (lane == 0) out[warp] = p + fcb[0];
    }
}

// =================== host orchestration ===================
extern "C" void kernel_launch(void* const* d_in, const int* in_sizes, int n_in,
                              void* d_out, int out_size) {
    const float* x        = (const float*)d_in[0];
    const int*   ei       = (const int*)  d_in[1];
    const float* W1       = (const float*)d_in[2];
    const float* att_src1 = (const float*)d_in[3];
    const float* att_dst1 = (const float*)d_in[4];
    const float* b1       = (const float*)d_in[5];
    const float* W2       = (const float*)d_in[6];
    const float* att_src2 = (const float*)d_in[7];
    const float* att_dst2 = (const float*)d_in[8];
    const float* b2       = (const float*)d_in[9];
    const float* fc_W     = (const float*)d_in[10];
    const float* fc_b     = (const float*)d_in[11];
    float* out = (float*)d_out;

    uint *x2p, *hh1, *hh2;
    float *as1, *ad1, *as2, *ad2;
    uint2 *bp1, *bp2;
    cudaGetSymbolAddress((void**)&x2p, g_x2h);
    cudaGetSymbolAddress((void**)&hh1, g_hh1);
    cudaGetSymbolAddress((void**)&hh2, g_hh2);
    cudaGetSymbolAddress((void**)&as1, g_asrc1);
    cudaGetSymbolAddress((void**)&ad1, g_adst1);
    cudaGetSymbolAddress((void**)&as2, g_asrc2);
    cudaGetSymbolAddress((void**)&ad2, g_adst2);
    cudaGetSymbolAddress((void**)&bp1, g_Bp1);
    cudaGetSymbolAddress((void**)&bp2, g_Bp2);

    static cudaStream_t s2 = nullptr;
    static cudaEvent_t evFork = nullptr, evF = nullptr, evG = nullptr, evJ = nullptr;
    if (s2 == nullptr) {
        cudaStreamCreateWithFlags(&s2, cudaStreamNonBlocking);
        cudaEventCreateWithFlags(&evFork, cudaEventDisableTiming);
        cudaEventCreateWithFlags(&evF, cudaEventDisableTiming);
        cudaEventCreateWithFlags(&evG, cudaEventDisableTiming);
        cudaEventCreateWithFlags(&evJ, cudaEventDisableTiming);
    }

    cudaEventRecord(evFork, 0);
    cudaStreamWaitEvent(s2, evFork, 0);

    // main: ELL build (cnt starts at 0 by invariant)
    fill_kernel<<<(Ee / 4 + 255) / 256, 256>>>(ei);
    cudaEventRecord(evF, 0);

    // s2: merged weight prep + full layer-1 GEMM (writes layer-1 buffers)
    bprep_all_kernel<<<(12 * 512 + 255) / 256, 256, 0, s2>>>(W1, W2);
    gemm_att_kernel<128, false><<<(Nn + 63) / 64, 128, 0, s2>>>(
        x, bp1, att_src1, att_dst1, hh1, as1, ad1, 0, Nn);
    cudaEventRecord(evG, s2);

    // pipelined halves: layer-2 GEMM writes separate buffers -> race-free
    cudaStreamWaitEvent(0, evG, 0);      // main agg1a needs gemm1 (s2)
    cudaStreamWaitEvent(s2, evF, 0);     // s2 agg1b needs ELL (main)

    aggregate_kernel<false, false><<<(H1 * 32 + AGG_W * 32 - 1) / (AGG_W * 32), AGG_W * 32>>>(
        hh1, as1, ad1, b1, nullptr, nullptr, (float*)x2p, 0, H1);
    gemm_att_kernel<64, true><<<(H1 + 63) / 64, 128>>>(
        x2p, bp2, att_src2, att_dst2, hh2, as2, ad2, 0, H1);

    aggregate_kernel<false, false><<<((Nn - H1) * 32 + AGG_W * 32 - 1) / (AGG_W * 32), AGG_W * 32, 0, s2>>>(
        hh1, as1, ad1, b1, nullptr, nullptr, (float*)x2p, H1, Nn);
    gemm_att_kernel<64, true><<<(Nn - H1 + 63) / 64, 128, 0, s2>>>(
        x2p, bp2, att_src2, att_dst2, hh2, as2, ad2, H1, Nn);
    cudaEventRecord(evJ, s2);

    // final aggregate (needs both halves of layer-2 buffers)
    cudaStreamWaitEvent(0, evJ, 0);
    aggregate_kernel<true, true><<<(Nn * 32 + AGG_W * 32 - 1) / (AGG_W * 32), AGG_W * 32>>>(
        hh2, as2, ad2, b2, fc_W, fc_b, out, 0, Nn);
}

// round 14
// speedup vs baseline: 1.0157x; 1.0157x over previous
#include <cuda_runtime.h>
#include <cuda_fp16.h>

#define Nn 50000
#define Ee 800000
#define NEG_SLOPE 0.2f
#define CAP 128            // ELL row capacity (real edges only; Poisson(17) in-degree)
#define H1 25024           // node split point (multiple of 64)

typedef unsigned int uint;
typedef unsigned long long u64;

// ---------------- scratch ----------------
__device__ uint   g_hh1[Nn * 64];    // layer-1 h as half2 units
__device__ uint   g_hh2[Nn * 64];    // layer-2 h as half2 units (double buffer)
__device__ uint   g_x2h[Nn * 32];    // layer-1 output as half2 units
__device__ float  g_asrc1[Nn * 2];
__device__ float  g_adst1[Nn * 2];
__device__ float  g_asrc2[Nn * 2];
__device__ float  g_adst2[Nn * 2];
__device__ int    g_cnt[Nn];         // INVARIANT: zero outside fill->agg2 window
__device__ int    g_ell[Nn * CAP];   // padded adjacency (real edges; self-loop implicit)
__device__ uint2  g_Bp1[8 * 512];    // layer-1 W fragments (K=128)
__device__ uint2  g_Bp2[4 * 512];    // layer-2 W fragments (K=64)

// ---------------- helpers ----------------
__device__ __forceinline__ uint packh2(float a, float b) {
    __half2 h = __floats2half2_rn(a, b);
    return *(uint*)&h;
}
__device__ __forceinline__ void mma16(float* c, const uint* a, uint b0, uint b1) {
    asm volatile(
        "mma.sync.aligned.m16n8k16.row.col.f32.f16.f16.f32 "
        "{%0,%1,%2,%3},{%4,%5,%6,%7},{%8,%9},{%0,%1,%2,%3};"
        : "+f"(c[0]), "+f"(c[1]), "+f"(c[2]), "+f"(c[3])
        : "r"(a[0]), "r"(a[1]), "r"(a[2]), "r"(a[3]), "r"(b0), "r"(b1));
}
__device__ __forceinline__ u64 packf2(float x, float y) {
    u64 u; asm("mov.b64 %0, {%1,%2};" : "=l"(u) : "f"(x), "f"(y)); return u;
}
__device__ __forceinline__ float2 unpackf2(u64 u) {
    float2 f; asm("mov.b64 {%0,%1}, %2;" : "=f"(f.x), "=f"(f.y) : "l"(u)); return f;
}
__device__ __forceinline__ void fma_f32x2(u64& acc, u64 h, u64 a) {
    asm("fma.rn.f32x2 %0, %1, %2, %0;" : "+l"(acc) : "l"(h), "l"(a));
}

// =================== ELL build (cnt starts at 0 by countdown invariant) ===================
__global__ void fill_kernel(const int* __restrict__ ei) {
    int i = blockIdx.x * blockDim.x + threadIdx.x;
    if (i >= Ee / 4) return;
    int4 s = ((const int4*)ei)[i];
    int4 d = ((const int4*)(ei + Ee))[i];
    int o;
    o = atomicAdd(&g_cnt[d.x], 1); if (o < CAP) g_ell[(d.x << 7) + o] = s.x;
    o = atomicAdd(&g_cnt[d.y], 1); if (o < CAP) g_ell[(d.y << 7) + o] = s.y;
    o = atomicAdd(&g_cnt[d.z], 1); if (o < CAP) g_ell[(d.z << 7) + o] = s.z;
    o = atomicAdd(&g_cnt[d.w], 1); if (o < CAP) g_ell[(d.w << 7) + o] = s.w;
}

// =================== merged B fragment prep (both layers) ===================
__device__ __forceinline__ void bfrag(const float* __restrict__ W, uint2* __restrict__ Bp, int e) {
    int ks   = e >> 9;
    int rem  = e & 511;
    int tp   = rem >> 5;
    int lane = rem & 31;
    int g = lane >> 2, t = lane & 3;
    int k0 = ks * 16 + 2 * t;
    int n  = tp * 8 + g;
    uint2 p;
    p.x = packh2(W[k0 * 128 + n],       W[(k0 + 1) * 128 + n]);
    p.y = packh2(W[(k0 + 8) * 128 + n], W[(k0 + 9) * 128 + n]);
    Bp[e] = p;
}
__global__ void bprep_all_kernel(const float* __restrict__ W1, const float* __restrict__ W2) {
    int e = blockIdx.x * blockDim.x + threadIdx.x;
    if (e < 8 * 512)       bfrag(W1, g_Bp1, e);
    else if (e < 12 * 512) bfrag(W2, g_Bp2, e - 8 * 512);
}

// =================== GEMM (fp16 HMMA, fp32 acc) + fused attention dots ===================
template <int K, bool HALF_IN>
__global__ void __launch_bounds__(128) gemm_att_kernel(const void* __restrict__ Xv,
                                                       const uint2* __restrict__ Bp,
                                                       const float* __restrict__ asv,
                                                       const float* __restrict__ adv,
                                                       uint* __restrict__ hhOut,
                                                       float* __restrict__ asrcOut,
                                                       float* __restrict__ adstOut,
                                                       int rowOff, int rowLim) {
    int w = threadIdx.x >> 5, lane = threadIdx.x & 31;
    int g = lane >> 2, t = lane & 3;
    int rowb = rowOff + blockIdx.x * 64 + w * 16;
    int r0 = rowb + g, r1 = r0 + 8;
    bool p0 = r0 < rowLim, p1 = r1 < rowLim;
    const float* Xf = (const float*)Xv;
    const uint*  Xh = (const uint*)Xv;

    float acc[16][4] = {};
#pragma unroll
    for (int ks = 0; ks < K / 16; ks++) {
        int kA = ks * 16 + 2 * t;
        uint a[4];
        if (HALF_IN) {
            a[0] = p0 ? Xh[(r0 * K + kA) >> 1]     : 0u;
            a[1] = p1 ? Xh[(r1 * K + kA) >> 1]     : 0u;
            a[2] = p0 ? Xh[(r0 * K + kA + 8) >> 1] : 0u;
            a[3] = p1 ? Xh[(r1 * K + kA + 8) >> 1] : 0u;
        } else {
            float2 f0 = p0 ? *(const float2*)&Xf[r0 * K + kA]     : make_float2(0.f, 0.f);
            float2 f1 = p1 ? *(const float2*)&Xf[r1 * K + kA]     : make_float2(0.f, 0.f);
            float2 f2 = p0 ? *(const float2*)&Xf[r0 * K + kA + 8] : make_float2(0.f, 0.f);
            float2 f3 = p1 ? *(const float2*)&Xf[r1 * K + kA + 8] : make_float2(0.f, 0.f);
            a[0] = packh2(f0.x, f0.y);
            a[1] = packh2(f1.x, f1.y);
            a[2] = packh2(f2.x, f2.y);
            a[3] = packh2(f3.x, f3.y);
        }
        const uint2* bp = Bp + ks * 512 + lane;
#pragma unroll
        for (int tp = 0; tp < 16; tp++) {
            uint2 b = bp[tp * 32];
            mma16(acc[tp], a, b.x, b.y);
        }
    }

#pragma unroll
    for (int n = 0; n < 16; n++) {
        int c = n * 8 + 2 * t;
        if (p0) hhOut[(r0 * 128 + c) >> 1] = packh2(acc[n][0], acc[n][1]);
        if (p1) hhOut[(r1 * 128 + c) >> 1] = packh2(acc[n][2], acc[n][3]);
    }

    float sa[2][2] = {};
    float sd_[2][2] = {};
#pragma unroll
    for (int n = 0; n < 16; n++) {
        int c = n * 8 + 2 * t;
        float v0 = asv[c], v1 = asv[c + 1];
        float u0 = adv[c], u1 = adv[c + 1];
        int hh = n >> 3;
        sa[0][hh] += acc[n][0] * v0 + acc[n][1] * v1;
        sa[1][hh] += acc[n][2] * v0 + acc[n][3] * v1;
        sd_[0][hh] += acc[n][0] * u0 + acc[n][1] * u1;
        sd_[1][hh] += acc[n][2] * u0 + acc[n][3] * u1;
    }
#pragma unroll
    for (int rh = 0; rh < 2; rh++)
#pragma unroll
        for (int hh = 0; hh < 2; hh++) {
            sa[rh][hh] += __shfl_xor_sync(~0u, sa[rh][hh], 1);
            sa[rh][hh] += __shfl_xor_sync(~0u, sa[rh][hh], 2);
            sd_[rh][hh] += __shfl_xor_sync(~0u, sd_[rh][hh], 1);
            sd_[rh][hh] += __shfl_xor_sync(~0u, sd_[rh][hh], 2);
        }
    if (t == 0) {
        if (p0) {
            asrcOut[r0 * 2] = sa[0][0]; asrcOut[r0 * 2 + 1] = sa[0][1];
            adstOut[r0 * 2] = sd_[0][0]; adstOut[r0 * 2 + 1] = sd_[0][1];
        }
        if (p1) {
            asrcOut[r1 * 2] = sa[1][0]; asrcOut[r1 * 2 + 1] = sa[1][1];
            adstOut[r1 * 2] = sd_[1][0]; adstOut[r1 * 2 + 1] = sd_[1][1];
        }
    }
}

// =================== aggregate over node range [n0, n1) ===================
// smem-staged exp values; unnormalized accumulate, scale by 1/S at the end.
template <bool FC, bool RESET>
__global__ void aggregate_kernel(const uint* __restrict__ hh,
                                 const float* __restrict__ asrc,
                                 const float* __restrict__ adst,
                                 const float* __restrict__ bias,
                                 const float* __restrict__ fcW,
                                 const float* __restrict__ fcb,
                                 float* __restrict__ out,
                                 int n0, int n1) {
    __shared__ int   s_src[8][32];
    __shared__ float s_p[8][64];     // [w][2*j + head]
    int tid = threadIdx.x;
    int wiw = tid >> 5;
    int warp = n0 + ((blockIdx.x * blockDim.x + tid) >> 5);
    int lane = tid & 31;
    if (warp >= n1) return;
    int base = warp << 7;
    int cnt = min(g_cnt[warp], CAP);
    float2 ad = *(const float2*)&adst[warp * 2];
    bool lo = (lane < 16);

    // self-loop logit
    float2 aself = *(const float2*)&asrc[warp * 2];
    float se0 = aself.x + ad.x; se0 = se0 > 0.f ? se0 : NEG_SLOPE * se0;
    float se1 = aself.y + ad.y; se1 = se1 > 0.f ? se1 : NEG_SLOPE * se1;
    se0 = __expf(fminf(se0, 60.f));
    se1 = __expf(fminf(se1, 60.f));

    // pass 1: edge logits + exp + sum; first 32 edges staged to smem
    float s0 = (lane == 0) ? se0 : 0.f;
    float s1 = (lane == 0) ? se1 : 0.f;
    if (lane < cnt) {
        int s = g_ell[base + lane];
        float2 as = *(const float2*)&asrc[s * 2];
        float e0 = as.x + ad.x; e0 = e0 > 0.f ? e0 : NEG_SLOPE * e0;
        float e1 = as.y + ad.y; e1 = e1 > 0.f ? e1 : NEG_SLOPE * e1;
        float fp0 = __expf(fminf(e0, 60.f));
        float fp1 = __expf(fminf(e1, 60.f));
        s_src[wiw][lane] = s;
        s_p[wiw][2 * lane]     = fp0;
        s_p[wiw][2 * lane + 1] = fp1;
        s0 += fp0; s1 += fp1;
        for (int j = lane + 32; j < cnt; j += 32) {
            int s2 = g_ell[base + j];
            float2 a2 = *(const float2*)&asrc[s2 * 2];
            float q0 = a2.x + ad.x; q0 = q0 > 0.f ? q0 : NEG_SLOPE * q0;
            float q1 = a2.y + ad.y; q1 = q1 > 0.f ? q1 : NEG_SLOPE * q1;
            s0 += __expf(fminf(q0, 60.f));
            s1 += __expf(fminf(q1, 60.f));
        }
    }
    __syncwarp();
#pragma unroll
    for (int o = 16; o > 0; o >>= 1) {
        s0 += __shfl_xor_sync(~0u, s0, o);
        s1 += __shfl_xor_sync(~0u, s1, o);
    }
    float inv = lo ? 1.f / (s0 + 1e-16f) : 1.f / (s1 + 1e-16f);

    // pass 2: UNNORMALIZED weighted fp16 gather; self term first
    u64 acc01, acc23;
    {
        float a = lo ? se0 : se1;
        uint2 hu = *(const uint2*)&hh[warp * 64 + lane * 2];
        float2 f0 = __half22float2(*(__half2*)&hu.x);
        float2 f1 = __half22float2(*(__half2*)&hu.y);
        acc01 = packf2(a * f0.x, a * f0.y);
        acc23 = packf2(a * f1.x, a * f1.y);
    }
    const float* pb = &s_p[wiw][lo ? 0 : 1];
    int cn = min(32, cnt);
#pragma unroll 8
    for (int j = 0; j < cn; j++) {
        int   s = s_src[wiw][j];
        float a = pb[2 * j];
        u64 aa = packf2(a, a);
        uint2 hu = *(const uint2*)&hh[s * 64 + lane * 2];
        float2 f0 = __half22float2(*(__half2*)&hu.x);
        float2 f1 = __half22float2(*(__half2*)&hu.y);
        fma_f32x2(acc01, packf2(f0.x, f0.y), aa);
        fma_f32x2(acc23, packf2(f1.x, f1.y), aa);
    }
    float2 a01 = unpackf2(acc01), a23 = unpackf2(acc23);
    float4 acc = make_float4(a01.x, a01.y, a23.x, a23.y);

    // cold path: degree > 32 — recompute exp, accumulate unnormalized
    for (int jb = 32; jb < cnt; jb += 32) {
        int idx = jb + lane;
        int   ls = 0;
        float lp0 = 0.f, lp1 = 0.f;
        if (idx < cnt) {
            ls = g_ell[base + idx];
            float2 a2 = *(const float2*)&asrc[ls * 2];
            float q0 = a2.x + ad.x; q0 = q0 > 0.f ? q0 : NEG_SLOPE * q0;
            float q1 = a2.y + ad.y; q1 = q1 > 0.f ? q1 : NEG_SLOPE * q1;
            lp0 = __expf(fminf(q0, 60.f));
            lp1 = __expf(fminf(q1, 60.f));
        }
        int n = min(32, cnt - jb);
        for (int j = 0; j < n; j++) {
            int   s  = __shfl_sync(~0u, ls, j);
            float q0 = __shfl_sync(~0u, lp0, j);
            float q1 = __shfl_sync(~0u, lp1, j);
            float a = lo ? q0 : q1;
            uint2 hu = *(const uint2*)&hh[s * 64 + lane * 2];
            float2 f0 = __half22float2(*(__half2*)&hu.x);
            float2 f1 = __half22float2(*(__half2*)&hu.y);
            acc.x += a * f0.x; acc.y += a * f0.y; acc.z += a * f1.x; acc.w += a * f1.y;
        }
    }

    // normalize, then head mean
    acc.x *= inv; acc.y *= inv; acc.z *= inv; acc.w *= inv;
    float4 o4;
    o4.x = (acc.x + __shfl_xor_sync(~0u, acc.x, 16)) * 0.5f;
    o4.y = (acc.y + __shfl_xor_sync(~0u, acc.y, 16)) * 0.5f;
    o4.z = (acc.z + __shfl_xor_sync(~0u, acc.z, 16)) * 0.5f;
    o4.w = (acc.w + __shfl_xor_sync(~0u, acc.w, 16)) * 0.5f;

    if (RESET) {
        if (lane == 0) g_cnt[warp] = 0;   // restore countdown invariant for next replay
    }

    if (!FC) {
        if (lane < 16) {
            float4 b4 = *(const float4*)&bias[lane * 4];
            o4.x = fmaxf(o4.x + b4.x, 0.f);
            o4.y = fmaxf(o4.y + b4.y, 0.f);
            o4.z = fmaxf(o4.z + b4.z, 0.f);
            o4.w = fmaxf(o4.w + b4.w, 0.f);
            uint2 p;
            p.x = packh2(o4.x, o4.y);
            p.y = packh2(o4.z, o4.w);
            *(uint2*)&((uint*)out)[warp * 32 + lane * 2] = p;
        }
    } else {
        float p = 0.f;
        if (lane < 16) {
            float4 b4 = *(const float4*)&bias[lane * 4];
            float4 w4 = *(const float4*)&fcW[lane * 4];
            p  = fmaxf(o4.x + b4.x, 0.f) * w4.x;
            p += fmaxf(o4.y + b4.y, 0.f) * w4.y;
            p += fmaxf(o4.z + b4.z, 0.f) * w4.z;
            p += fmaxf(o4.w + b4.w, 0.f) * w4.w;
        }
#pragma unroll
        for (int o = 8; o > 0; o >>= 1) p += __shfl_xor_sync(~0u, p, o);
        if (lane == 0) out[warp] = p + fcb[0];
    }
}

// =================== host orchestration ===================
extern "C" void kernel_launch(void* const* d_in, const int* in_sizes, int n_in,
                              void* d_out, int out_size) {
    const float* x        = (const float*)d_in[0];
    const int*   ei       = (const int*)  d_in[1];
    const float* W1       = (const float*)d_in[2];
    const float* att_src1 = (const float*)d_in[3];
    const float* att_dst1 = (const float*)d_in[4];
    const float* b1       = (const float*)d_in[5];
    const float* W2       = (const float*)d_in[6];
    const float* att_src2 = (const float*)d_in[7];
    const float* att_dst2 = (const float*)d_in[8];
    const float* b2       = (const float*)d_in[9];
    const float* fc_W     = (const float*)d_in[10];
    const float* fc_b     = (const float*)d_in[11];
    float* out = (float*)d_out;

    uint *x2p, *hh1, *hh2;
    float *as1, *ad1, *as2, *ad2;
    uint2 *bp1, *bp2;
    cudaGetSymbolAddress((void**)&x2p, g_x2h);
    cudaGetSymbolAddress((void**)&hh1, g_hh1);
    cudaGetSymbolAddress((void**)&hh2, g_hh2);
    cudaGetSymbolAddress((void**)&as1, g_asrc1);
    cudaGetSymbolAddress((void**)&ad1, g_adst1);
    cudaGetSymbolAddress((void**)&as2, g_asrc2);
    cudaGetSymbolAddress((void**)&ad2, g_adst2);
    cudaGetSymbolAddress((void**)&bp1, g_Bp1);
    cudaGetSymbolAddress((void**)&bp2, g_Bp2);

    static cudaStream_t s2 = nullptr;
    static cudaEvent_t evFork = nullptr, evF = nullptr, evG = nullptr, evJ = nullptr;
    if (s2 == nullptr) {
        cudaStreamCreateWithFlags(&s2, cudaStreamNonBlocking);
        cudaEventCreateWithFlags(&evFork, cudaEventDisableTiming);
        cudaEventCreateWithFlags(&evF, cudaEventDisableTiming);
        cudaEventCreateWithFlags(&evG, cudaEventDisableTiming);
        cudaEventCreateWithFlags(&evJ, cudaEventDisableTiming);
    }

    cudaEventRecord(evFork, 0);
    cudaStreamWaitEvent(s2, evFork, 0);

    // main: ELL build (cnt starts at 0 by invariant)
    fill_kernel<<<(Ee / 4 + 255) / 256, 256>>>(ei);
    cudaEventRecord(evF, 0);

    // s2: merged weight prep + full layer-1 GEMM (writes layer-1 buffers)
    bprep_all_kernel<<<(12 * 512 + 255) / 256, 256, 0, s2>>>(W1, W2);
    gemm_att_kernel<128, false><<<(Nn + 63) / 64, 128, 0, s2>>>(
        x, bp1, att_src1, att_dst1, hh1, as1, ad1, 0, Nn);
    cudaEventRecord(evG, s2);

    // pipelined halves: layer-2 GEMM writes separate buffers -> race-free
    cudaStreamWaitEvent(0, evG, 0);      // main agg1a needs gemm1 (s2)
    cudaStreamWaitEvent(s2, evF, 0);     // s2 agg1b needs ELL (main)

    aggregate_kernel<false, false><<<(H1 * 32 + 255) / 256, 256>>>(
        hh1, as1, ad1, b1, nullptr, nullptr, (float*)x2p, 0, H1);
    gemm_att_kernel<64, true><<<(H1 + 63) / 64, 128>>>(
        x2p, bp2, att_src2, att_dst2, hh2, as2, ad2, 0, H1);

    aggregate_kernel<false, false><<<((Nn - H1) * 32 + 255) / 256, 256, 0, s2>>>(
        hh1, as1, ad1, b1, nullptr, nullptr, (float*)x2p, H1, Nn);
    gemm_att_kernel<64, true><<<(Nn - H1 + 63) / 64, 128, 0, s2>>>(
        x2p, bp2, att_src2, att_dst2, hh2, as2, ad2, H1, Nn);
    cudaEventRecord(evJ, s2);

    // final aggregate (needs both halves of layer-2 buffers)
    cudaStreamWaitEvent(0, evJ, 0);
    aggregate_kernel<true, true><<<(Nn * 32 + 255) / 256, 256>>>(
        hh2, as2, ad2, b2, fc_W, fc_b, out, 0, Nn);
}

// round 15
// speedup vs baseline: 1.0927x; 1.0758x over previous
#include <cuda_runtime.h>
#include <cuda_fp16.h>

#define Nn 50000
#define Ee 800000
#define NEG_SLOPE 0.2f
#define CAP 128            // ELL row capacity (real edges only; Poisson(17) in-degree)
#define H1 25024           // node split point (multiple of 64)

typedef unsigned int uint;
typedef unsigned long long u64;

// ---------------- scratch ----------------
__device__ uint   g_hh1[Nn * 64];    // layer-1 h as half2 units
__device__ uint   g_hh2[Nn * 64];    // layer-2 h as half2 units (double buffer)
__device__ uint   g_x2h[Nn * 32];    // layer-1 output as half2 units
__device__ float  g_asrc1[Nn * 2];
__device__ float  g_adst1[Nn * 2];
__device__ float  g_asrc2[Nn * 2];
__device__ float  g_adst2[Nn * 2];
__device__ int    g_cnt[Nn];         // INVARIANT: zero outside fill->agg2 window
__device__ int    g_ell[Nn * CAP];   // padded adjacency (real edges; self-loop implicit)
__device__ uint2  g_Bp1[8 * 512];    // layer-1 W fragments (K=128)
__device__ uint2  g_Bp2[4 * 512];    // layer-2 W fragments (K=64)

// ---------------- helpers ----------------
__device__ __forceinline__ uint packh2(float a, float b) {
    __half2 h = __floats2half2_rn(a, b);
    return *(uint*)&h;
}
__device__ __forceinline__ void mma16(float* c, const uint* a, uint b0, uint b1) {
    asm volatile(
        "mma.sync.aligned.m16n8k16.row.col.f32.f16.f16.f32 "
        "{%0,%1,%2,%3},{%4,%5,%6,%7},{%8,%9},{%0,%1,%2,%3};"
        : "+f"(c[0]), "+f"(c[1]), "+f"(c[2]), "+f"(c[3])
        : "r"(a[0]), "r"(a[1]), "r"(a[2]), "r"(a[3]), "r"(b0), "r"(b1));
}
__device__ __forceinline__ u64 packf2(float x, float y) {
    u64 u; asm("mov.b64 %0, {%1,%2};" : "=l"(u) : "f"(x), "f"(y)); return u;
}
__device__ __forceinline__ float2 unpackf2(u64 u) {
    float2 f; asm("mov.b64 {%0,%1}, %2;" : "=f"(f.x), "=f"(f.y) : "l"(u)); return f;
}
__device__ __forceinline__ void fma_f32x2(u64& acc, u64 h, u64 a) {
    asm("fma.rn.f32x2 %0, %1, %2, %0;" : "+l"(acc) : "l"(h), "l"(a));
}
__device__ __forceinline__ u64 add_f32x2(u64 a, u64 b) {
    u64 r; asm("add.rn.f32x2 %0, %1, %2;" : "=l"(r) : "l"(a), "l"(b)); return r;
}
__device__ __forceinline__ u64 mul_f32x2(u64 a, u64 b) {
    u64 r; asm("mul.rn.f32x2 %0, %1, %2;" : "=l"(r) : "l"(a), "l"(b)); return r;
}

// =================== ELL build (cnt starts at 0 by countdown invariant) ===================
__global__ void fill_kernel(const int* __restrict__ ei) {
    int i = blockIdx.x * blockDim.x + threadIdx.x;
    if (i >= Ee / 4) return;
    int4 s = ((const int4*)ei)[i];
    int4 d = ((const int4*)(ei + Ee))[i];
    int o;
    o = atomicAdd(&g_cnt[d.x], 1); if (o < CAP) g_ell[(d.x << 7) + o] = s.x;
    o = atomicAdd(&g_cnt[d.y], 1); if (o < CAP) g_ell[(d.y << 7) + o] = s.y;
    o = atomicAdd(&g_cnt[d.z], 1); if (o < CAP) g_ell[(d.z << 7) + o] = s.z;
    o = atomicAdd(&g_cnt[d.w], 1); if (o < CAP) g_ell[(d.w << 7) + o] = s.w;
}

// =================== merged B fragment prep (both layers) ===================
__device__ __forceinline__ void bfrag(const float* __restrict__ W, uint2* __restrict__ Bp, int e) {
    int ks   = e >> 9;
    int rem  = e & 511;
    int tp   = rem >> 5;
    int lane = rem & 31;
    int g = lane >> 2, t = lane & 3;
    int k0 = ks * 16 + 2 * t;
    int n  = tp * 8 + g;
    uint2 p;
    p.x = packh2(W[k0 * 128 + n],       W[(k0 + 1) * 128 + n]);
    p.y = packh2(W[(k0 + 8) * 128 + n], W[(k0 + 9) * 128 + n]);
    Bp[e] = p;
}
__global__ void bprep_all_kernel(const float* __restrict__ W1, const float* __restrict__ W2) {
    int e = blockIdx.x * blockDim.x + threadIdx.x;
    if (e < 8 * 512)       bfrag(W1, g_Bp1, e);
    else if (e < 12 * 512) bfrag(W2, g_Bp2, e - 8 * 512);
}

// =================== GEMM (fp16 HMMA, fp32 acc) + fused attention dots ===================
template <int K, bool HALF_IN>
__global__ void __launch_bounds__(128) gemm_att_kernel(const void* __restrict__ Xv,
                                                       const uint2* __restrict__ Bp,
                                                       const float* __restrict__ asv,
                                                       const float* __restrict__ adv,
                                                       uint* __restrict__ hhOut,
                                                       float* __restrict__ asrcOut,
                                                       float* __restrict__ adstOut,
                                                       int rowOff, int rowLim) {
    int w = threadIdx.x >> 5, lane = threadIdx.x & 31;
    int g = lane >> 2, t = lane & 3;
    int rowb = rowOff + blockIdx.x * 64 + w * 16;
    int r0 = rowb + g, r1 = r0 + 8;
    bool p0 = r0 < rowLim, p1 = r1 < rowLim;
    const float* Xf = (const float*)Xv;
    const uint*  Xh = (const uint*)Xv;

    float acc[16][4] = {};
#pragma unroll
    for (int ks = 0; ks < K / 16; ks++) {
        int kA = ks * 16 + 2 * t;
        uint a[4];
        if (HALF_IN) {
            a[0] = p0 ? Xh[(r0 * K + kA) >> 1]     : 0u;
            a[1] = p1 ? Xh[(r1 * K + kA) >> 1]     : 0u;
            a[2] = p0 ? Xh[(r0 * K + kA + 8) >> 1] : 0u;
            a[3] = p1 ? Xh[(r1 * K + kA + 8) >> 1] : 0u;
        } else {
            float2 f0 = p0 ? *(const float2*)&Xf[r0 * K + kA]     : make_float2(0.f, 0.f);
            float2 f1 = p1 ? *(const float2*)&Xf[r1 * K + kA]     : make_float2(0.f, 0.f);
            float2 f2 = p0 ? *(const float2*)&Xf[r0 * K + kA + 8] : make_float2(0.f, 0.f);
            float2 f3 = p1 ? *(const float2*)&Xf[r1 * K + kA + 8] : make_float2(0.f, 0.f);
            a[0] = packh2(f0.x, f0.y);
            a[1] = packh2(f1.x, f1.y);
            a[2] = packh2(f2.x, f2.y);
            a[3] = packh2(f3.x, f3.y);
        }
        const uint2* bp = Bp + ks * 512 + lane;
#pragma unroll
        for (int tp = 0; tp < 16; tp++) {
            uint2 b = bp[tp * 32];
            mma16(acc[tp], a, b.x, b.y);
        }
    }

#pragma unroll
    for (int n = 0; n < 16; n++) {
        int c = n * 8 + 2 * t;
        if (p0) hhOut[(r0 * 128 + c) >> 1] = packh2(acc[n][0], acc[n][1]);
        if (p1) hhOut[(r1 * 128 + c) >> 1] = packh2(acc[n][2], acc[n][3]);
    }

    float sa[2][2] = {};
    float sd_[2][2] = {};
#pragma unroll
    for (int n = 0; n < 16; n++) {
        int c = n * 8 + 2 * t;
        float v0 = asv[c], v1 = asv[c + 1];
        float u0 = adv[c], u1 = adv[c + 1];
        int hh = n >> 3;
        sa[0][hh] += acc[n][0] * v0 + acc[n][1] * v1;
        sa[1][hh] += acc[n][2] * v0 + acc[n][3] * v1;
        sd_[0][hh] += acc[n][0] * u0 + acc[n][1] * u1;
        sd_[1][hh] += acc[n][2] * u0 + acc[n][3] * u1;
    }
#pragma unroll
    for (int rh = 0; rh < 2; rh++)
#pragma unroll
        for (int hh = 0; hh < 2; hh++) {
            sa[rh][hh] += __shfl_xor_sync(~0u, sa[rh][hh], 1);
            sa[rh][hh] += __shfl_xor_sync(~0u, sa[rh][hh], 2);
            sd_[rh][hh] += __shfl_xor_sync(~0u, sd_[rh][hh], 1);
            sd_[rh][hh] += __shfl_xor_sync(~0u, sd_[rh][hh], 2);
        }
    if (t == 0) {
        if (p0) {
            asrcOut[r0 * 2] = sa[0][0]; asrcOut[r0 * 2 + 1] = sa[0][1];
            adstOut[r0 * 2] = sd_[0][0]; adstOut[r0 * 2 + 1] = sd_[0][1];
        }
        if (p1) {
            asrcOut[r1 * 2] = sa[1][0]; asrcOut[r1 * 2 + 1] = sa[1][1];
            adstOut[r1 * 2] = sd_[1][0]; adstOut[r1 * 2 + 1] = sd_[1][1];
        }
    }
}

// =================== aggregate over node range [n0, n1) ===================
// 16 lanes per edge (LDG.128), 2 edges/iter; self appended as pseudo-edge;
// unnormalized accumulate, normalize (x0.5 head-mean folded) at the end.
template <bool FC, bool RESET>
__global__ void aggregate_kernel(const uint* __restrict__ hh,
                                 const float* __restrict__ asrc,
                                 const float* __restrict__ adst,
                                 const float* __restrict__ bias,
                                 const float* __restrict__ fcW,
                                 const float* __restrict__ fcb,
                                 float* __restrict__ out,
                                 int n0, int n1) {
    __shared__ int   s_src[8][34];
    __shared__ float s_p[8][68];     // [w][2*j + head]
    int tid = threadIdx.x;
    int wiw = tid >> 5;
    int warp = n0 + ((blockIdx.x * blockDim.x + tid) >> 5);
    int lane = tid & 31;
    if (warp >= n1) return;
    int base = warp << 7;
    int cnt = min(g_cnt[warp], CAP);
    float2 ad = *(const float2*)&adst[warp * 2];
    int t = lane & 15;               // sublane: halves [8t, 8t+8)
    int p = lane >> 4;               // edge parity
    int hsel = (t >= 8) ? 1 : 0;     // head of this sublane's channels

    // self-loop logit
    float2 aself = *(const float2*)&asrc[warp * 2];
    float se0 = aself.x + ad.x; se0 = se0 > 0.f ? se0 : NEG_SLOPE * se0;
    float se1 = aself.y + ad.y; se1 = se1 > 0.f ? se1 : NEG_SLOPE * se1;
    se0 = __expf(fminf(se0, 60.f));
    se1 = __expf(fminf(se1, 60.f));

    int cn = min(32, cnt);
    // pass 1: edge logits + exp + sum; first 32 edges staged to smem
    float s0 = (lane == 0) ? se0 : 0.f;
    float s1 = (lane == 0) ? se1 : 0.f;
    if (lane < cnt) {
        int s = g_ell[base + lane];
        float2 as = *(const float2*)&asrc[s * 2];
        float e0 = as.x + ad.x; e0 = e0 > 0.f ? e0 : NEG_SLOPE * e0;
        float e1 = as.y + ad.y; e1 = e1 > 0.f ? e1 : NEG_SLOPE * e1;
        float fp0 = __expf(fminf(e0, 60.f));
        float fp1 = __expf(fminf(e1, 60.f));
        s_src[wiw][lane] = s;
        s_p[wiw][2 * lane]     = fp0;
        s_p[wiw][2 * lane + 1] = fp1;
        s0 += fp0; s1 += fp1;
        for (int j = lane + 32; j < cnt; j += 32) {
            int s2 = g_ell[base + j];
            float2 a2 = *(const float2*)&asrc[s2 * 2];
            float q0 = a2.x + ad.x; q0 = q0 > 0.f ? q0 : NEG_SLOPE * q0;
            float q1 = a2.y + ad.y; q1 = q1 > 0.f ? q1 : NEG_SLOPE * q1;
            s0 += __expf(fminf(q0, 60.f));
            s1 += __expf(fminf(q1, 60.f));
        }
    }
    if (lane == 0) {                 // append self as pseudo-edge cn
        s_src[wiw][cn] = warp;
        s_p[wiw][2 * cn]     = se0;
        s_p[wiw][2 * cn + 1] = se1;
    }
    __syncwarp();
#pragma unroll
    for (int o = 16; o > 0; o >>= 1) {
        s0 += __shfl_xor_sync(~0u, s0, o);
        s1 += __shfl_xor_sync(~0u, s1, o);
    }
    float inv0 = 0.5f / (s0 + 1e-16f);   // 0.5 = head-mean folded in
    float inv1 = 0.5f / (s1 + 1e-16f);

    // pass 2: UNNORMALIZED gather; 2 edges/iter, 1 LDG.128 per lane per edge-pair
    u64 acc0 = 0, acc1 = 0, acc2 = 0, acc3 = 0;
    int ce = cn + 1;                 // incl. self pseudo-edge
    const uint* hrow = hh + 4 * t;
#pragma unroll 4
    for (int j = p; j < ce; j += 2) {
        int s = s_src[wiw][j];
        float a = s_p[wiw][2 * j + hsel];
        u64 aa = packf2(a, a);
        uint4 hu = *(const uint4*)&hrow[s * 64];
        float2 f0 = __half22float2(*(__half2*)&hu.x);
        float2 f1 = __half22float2(*(__half2*)&hu.y);
        float2 f2 = __half22float2(*(__half2*)&hu.z);
        float2 f3 = __half22float2(*(__half2*)&hu.w);
        fma_f32x2(acc0, packf2(f0.x, f0.y), aa);
        fma_f32x2(acc1, packf2(f1.x, f1.y), aa);
        fma_f32x2(acc2, packf2(f2.x, f2.y), aa);
        fma_f32x2(acc3, packf2(f3.x, f3.y), aa);
    }
    // cold path: degree > 32 — recompute exp, parity-strided (no double count)
    for (int j = 32 + p; j < cnt; j += 2) {
        int s = g_ell[base + j];
        float2 a2 = *(const float2*)&asrc[s * 2];
        float q0 = a2.x + ad.x; q0 = q0 > 0.f ? q0 : NEG_SLOPE * q0;
        float q1 = a2.y + ad.y; q1 = q1 > 0.f ? q1 : NEG_SLOPE * q1;
        q0 = __expf(fminf(q0, 60.f));
        q1 = __expf(fminf(q1, 60.f));
        float a = hsel ? q1 : q0;
        u64 aa = packf2(a, a);
        uint4 hu = *(const uint4*)&hrow[s * 64];
        float2 f0 = __half22float2(*(__half2*)&hu.x);
        float2 f1 = __half22float2(*(__half2*)&hu.y);
        float2 f2 = __half22float2(*(__half2*)&hu.z);
        float2 f3 = __half22float2(*(__half2*)&hu.w);
        fma_f32x2(acc0, packf2(f0.x, f0.y), aa);
        fma_f32x2(acc1, packf2(f1.x, f1.y), aa);
        fma_f32x2(acc2, packf2(f2.x, f2.y), aa);
        fma_f32x2(acc3, packf2(f3.x, f3.y), aa);
    }

    // combine edge-parity halves (lane ^ 16 has same channels)
    acc0 = add_f32x2(acc0, __shfl_xor_sync(~0u, acc0, 16));
    acc1 = add_f32x2(acc1, __shfl_xor_sync(~0u, acc1, 16));
    acc2 = add_f32x2(acc2, __shfl_xor_sync(~0u, acc2, 16));
    acc3 = add_f32x2(acc3, __shfl_xor_sync(~0u, acc3, 16));
    // normalize per head (0.5 folded)
    float invh = hsel ? inv1 : inv0;
    u64 iv = packf2(invh, invh);
    acc0 = mul_f32x2(acc0, iv);
    acc1 = mul_f32x2(acc1, iv);
    acc2 = mul_f32x2(acc2, iv);
    acc3 = mul_f32x2(acc3, iv);
    // head mean: lane t pairs with lane t^8 (channel-aligned)
    acc0 = add_f32x2(acc0, __shfl_xor_sync(~0u, acc0, 8));
    acc1 = add_f32x2(acc1, __shfl_xor_sync(~0u, acc1, 8));
    acc2 = add_f32x2(acc2, __shfl_xor_sync(~0u, acc2, 8));
    acc3 = add_f32x2(acc3, __shfl_xor_sync(~0u, acc3, 8));

    if (RESET) {
        if (lane == 0) g_cnt[warp] = 0;   // restore countdown invariant
    }

    float2 c01 = unpackf2(acc0), c23 = unpackf2(acc1);
    float2 c45 = unpackf2(acc2), c67 = unpackf2(acc3);

    if (!FC) {
        if (lane < 8) {                   // lane covers channels 8*lane..8*lane+7
            float4 bA = *(const float4*)&bias[lane * 8];
            float4 bB = *(const float4*)&bias[lane * 8 + 4];
            float r0 = fmaxf(c01.x + bA.x, 0.f);
            float r1 = fmaxf(c01.y + bA.y, 0.f);
            float r2 = fmaxf(c23.x + bA.z, 0.f);
            float r3 = fmaxf(c23.y + bA.w, 0.f);
            float r4 = fmaxf(c45.x + bB.x, 0.f);
            float r5 = fmaxf(c45.y + bB.y, 0.f);
            float r6 = fmaxf(c67.x + bB.z, 0.f);
            float r7 = fmaxf(c67.y + bB.w, 0.f);
            uint4 pk;
            pk.x = packh2(r0, r1);
            pk.y = packh2(r2, r3);
            pk.z = packh2(r4, r5);
            pk.w = packh2(r6, r7);
            *(uint4*)&((uint*)out)[warp * 32 + lane * 4] = pk;
        }
    } else {
        float pp = 0.f;
        if (lane < 8) {
            float4 bA = *(const float4*)&bias[lane * 8];
            float4 bB = *(const float4*)&bias[lane * 8 + 4];
            float4 wA = *(const float4*)&fcW[lane * 8];
            float4 wB = *(const float4*)&fcW[lane * 8 + 4];
            pp  = fmaxf(c01.x + bA.x, 0.f) * wA.x;
            pp += fmaxf(c01.y + bA.y, 0.f) * wA.y;
            pp += fmaxf(c23.x + bA.z, 0.f) * wA.z;
            pp += fmaxf(c23.y + bA.w, 0.f) * wA.w;
            pp += fmaxf(c45.x + bB.x, 0.f) * wB.x;
            pp += fmaxf(c45.y + bB.y, 0.f) * wB.y;
            pp += fmaxf(c67.x + bB.z, 0.f) * wB.z;
            pp += fmaxf(c67.y + bB.w, 0.f) * wB.w;
        }
#pragma unroll
        for (int o = 4; o > 0; o >>= 1) pp += __shfl_xor_sync(~0u, pp, o);
        if (lane == 0) out[warp] = pp + fcb[0];
    }
}

// =================== host orchestration ===================
extern "C" void kernel_launch(void* const* d_in, const int* in_sizes, int n_in,
                              void* d_out, int out_size) {
    const float* x        = (const float*)d_in[0];
    const int*   ei       = (const int*)  d_in[1];
    const float* W1       = (const float*)d_in[2];
    const float* att_src1 = (const float*)d_in[3];
    const float* att_dst1 = (const float*)d_in[4];
    const float* b1       = (const float*)d_in[5];
    const float* W2       = (const float*)d_in[6];
    const float* att_src2 = (const float*)d_in[7];
    const float* att_dst2 = (const float*)d_in[8];
    const float* b2       = (const float*)d_in[9];
    const float* fc_W     = (const float*)d_in[10];
    const float* fc_b     = (const float*)d_in[11];
    float* out = (float*)d_out;

    uint *x2p, *hh1, *hh2;
    float *as1, *ad1, *as2, *ad2;
    uint2 *bp1, *bp2;
    cudaGetSymbolAddress((void**)&x2p, g_x2h);
    cudaGetSymbolAddress((void**)&hh1, g_hh1);
    cudaGetSymbolAddress((void**)&hh2, g_hh2);
    cudaGetSymbolAddress((void**)&as1, g_asrc1);
    cudaGetSymbolAddress((void**)&ad1, g_adst1);
    cudaGetSymbolAddress((void**)&as2, g_asrc2);
    cudaGetSymbolAddress((void**)&ad2, g_adst2);
    cudaGetSymbolAddress((void**)&bp1, g_Bp1);
    cudaGetSymbolAddress((void**)&bp2, g_Bp2);

    static cudaStream_t s2 = nullptr;
    static cudaEvent_t evFork = nullptr, evF = nullptr, evG = nullptr, evJ = nullptr;
    if (s2 == nullptr) {
        cudaStreamCreateWithFlags(&s2, cudaStreamNonBlocking);
        cudaEventCreateWithFlags(&evFork, cudaEventDisableTiming);
        cudaEventCreateWithFlags(&evF, cudaEventDisableTiming);
        cudaEventCreateWithFlags(&evG, cudaEventDisableTiming);
        cudaEventCreateWithFlags(&evJ, cudaEventDisableTiming);
    }

    cudaEventRecord(evFork, 0);
    cudaStreamWaitEvent(s2, evFork, 0);

    // main: ELL build (cnt starts at 0 by invariant)
    fill_kernel<<<(Ee / 4 + 255) / 256, 256>>>(ei);
    cudaEventRecord(evF, 0);

    // s2: merged weight prep + full layer-1 GEMM (writes layer-1 buffers)
    bprep_all_kernel<<<(12 * 512 + 255) / 256, 256, 0, s2>>>(W1, W2);
    gemm_att_kernel<128, false><<<(Nn + 63) / 64, 128, 0, s2>>>(
        x, bp1, att_src1, att_dst1, hh1, as1, ad1, 0, Nn);
    cudaEventRecord(evG, s2);

    // pipelined halves: layer-2 GEMM writes separate buffers -> race-free
    cudaStreamWaitEvent(0, evG, 0);      // main agg1a needs gemm1 (s2)
    cudaStreamWaitEvent(s2, evF, 0);     // s2 agg1b needs ELL (main)

    aggregate_kernel<false, false><<<(H1 * 32 + 255) / 256, 256>>>(
        hh1, as1, ad1, b1, nullptr, nullptr, (float*)x2p, 0, H1);
    gemm_att_kernel<64, true><<<(H1 + 63) / 64, 128>>>(
        x2p, bp2, att_src2, att_dst2, hh2, as2, ad2, 0, H1);

    aggregate_kernel<false, false><<<((Nn - H1) * 32 + 255) / 256, 256, 0, s2>>>(
        hh1, as1, ad1, b1, nullptr, nullptr, (float*)x2p, H1, Nn);
    gemm_att_kernel<64, true><<<(Nn - H1 + 63) / 64, 128, 0, s2>>>(
        x2p, bp2, att_src2, att_dst2, hh2, as2, ad2, H1, Nn);
    cudaEventRecord(evJ, s2);

    // final aggregate (needs both halves of layer-2 buffers)
    cudaStreamWaitEvent(0, evJ, 0);
    aggregate_kernel<true, true><<<(Nn * 32 + 255) / 256, 256>>>(
        hh2, as2, ad2, b2, fc_W, fc_b, out, 0, Nn);
}

// round 16
// speedup vs baseline: 1.1571x; 1.0589x over previous
#include <cuda_runtime.h>
#include <cuda_fp16.h>

#define Nn 50000
#define Ee 800000
#define NEG_SLOPE 0.2f
#define CAP 128            // ELL row capacity (real edges only; Poisson(17) in-degree)
#define H1 25024           // node split point (multiple of 64)

typedef unsigned int uint;
typedef unsigned long long u64;

// ---------------- scratch ----------------
__device__ uint   g_hh1[Nn * 64];    // layer-1 h as half2 units
__device__ uint   g_hh2[Nn * 64];    // layer-2 h as half2 units (double buffer)
__device__ uint   g_x2h[Nn * 32];    // layer-1 output as half2 units
__device__ float  g_asrc1[Nn * 2];
__device__ float  g_adst1[Nn * 2];
__device__ float  g_asrc2[Nn * 2];
__device__ float  g_adst2[Nn * 2];
__device__ int    g_cnt[Nn];         // INVARIANT: zero outside fill->agg2 window
__device__ int    g_ell[Nn * CAP];   // padded adjacency (real edges; self-loop implicit)
__device__ uint2  g_Bp1[8 * 512];    // layer-1 W fragments (K=128)
__device__ uint2  g_Bp2[4 * 512];    // layer-2 W fragments (K=64)

// ---------------- helpers ----------------
__device__ __forceinline__ uint packh2(float a, float b) {
    __half2 h = __floats2half2_rn(a, b);
    return *(uint*)&h;
}
__device__ __forceinline__ void mma16(float* c, const uint* a, uint b0, uint b1) {
    asm volatile(
        "mma.sync.aligned.m16n8k16.row.col.f32.f16.f16.f32 "
        "{%0,%1,%2,%3},{%4,%5,%6,%7},{%8,%9},{%0,%1,%2,%3};"
        : "+f"(c[0]), "+f"(c[1]), "+f"(c[2]), "+f"(c[3])
        : "r"(a[0]), "r"(a[1]), "r"(a[2]), "r"(a[3]), "r"(b0), "r"(b1));
}
__device__ __forceinline__ u64 packf2(float x, float y) {
    u64 u; asm("mov.b64 %0, {%1,%2};" : "=l"(u) : "f"(x), "f"(y)); return u;
}
__device__ __forceinline__ float2 unpackf2(u64 u) {
    float2 f; asm("mov.b64 {%0,%1}, %2;" : "=f"(f.x), "=f"(f.y) : "l"(u)); return f;
}
__device__ __forceinline__ void fma_f32x2(u64& acc, u64 h, u64 a) {
    asm("fma.rn.f32x2 %0, %1, %2, %0;" : "+l"(acc) : "l"(h), "l"(a));
}

// =================== ELL build (cnt starts at 0 by countdown invariant) ===================
__global__ void fill_kernel(const int* __restrict__ ei) {
    int i = blockIdx.x * blockDim.x + threadIdx.x;
    if (i >= Ee / 4) return;
    int4 s = ((const int4*)ei)[i];
    int4 d = ((const int4*)(ei + Ee))[i];
    int o;
    o = atomicAdd(&g_cnt[d.x], 1); if (o < CAP) g_ell[(d.x << 7) + o] = s.x;
    o = atomicAdd(&g_cnt[d.y], 1); if (o < CAP) g_ell[(d.y << 7) + o] = s.y;
    o = atomicAdd(&g_cnt[d.z], 1); if (o < CAP) g_ell[(d.z << 7) + o] = s.z;
    o = atomicAdd(&g_cnt[d.w], 1); if (o < CAP) g_ell[(d.w << 7) + o] = s.w;
}

// =================== merged B fragment prep (both layers) ===================
__device__ __forceinline__ void bfrag(const float* __restrict__ W, uint2* __restrict__ Bp, int e) {
    int ks   = e >> 9;
    int rem  = e & 511;
    int tp   = rem >> 5;
    int lane = rem & 31;
    int g = lane >> 2, t = lane & 3;
    int k0 = ks * 16 + 2 * t;
    int n  = tp * 8 + g;
    uint2 p;
    p.x = packh2(W[k0 * 128 + n],       W[(k0 + 1) * 128 + n]);
    p.y = packh2(W[(k0 + 8) * 128 + n], W[(k0 + 9) * 128 + n]);
    Bp[e] = p;
}
__global__ void bprep_all_kernel(const float* __restrict__ W1, const float* __restrict__ W2) {
    int e = blockIdx.x * blockDim.x + threadIdx.x;
    if (e < 8 * 512)       bfrag(W1, g_Bp1, e);
    else if (e < 12 * 512) bfrag(W2, g_Bp2, e - 8 * 512);
}

// =================== GEMM (fp16 HMMA, fp32 acc) + fused attention dots ===================
template <int K, bool HALF_IN>
__global__ void __launch_bounds__(128) gemm_att_kernel(const void* __restrict__ Xv,
                                                       const uint2* __restrict__ Bp,
                                                       const float* __restrict__ asv,
                                                       const float* __restrict__ adv,
                                                       uint* __restrict__ hhOut,
                                                       float* __restrict__ asrcOut,
                                                       float* __restrict__ adstOut,
                                                       int rowOff, int rowLim) {
    int w = threadIdx.x >> 5, lane = threadIdx.x & 31;
    int g = lane >> 2, t = lane & 3;
    int rowb = rowOff + blockIdx.x * 64 + w * 16;
    int r0 = rowb + g, r1 = r0 + 8;
    bool p0 = r0 < rowLim, p1 = r1 < rowLim;
    const float* Xf = (const float*)Xv;
    const uint*  Xh = (const uint*)Xv;

    float acc[16][4] = {};
#pragma unroll
    for (int ks = 0; ks < K / 16; ks++) {
        int kA = ks * 16 + 2 * t;
        uint a[4];
        if (HALF_IN) {
            a[0] = p0 ? Xh[(r0 * K + kA) >> 1]     : 0u;
            a[1] = p1 ? Xh[(r1 * K + kA) >> 1]     : 0u;
            a[2] = p0 ? Xh[(r0 * K + kA + 8) >> 1] : 0u;
            a[3] = p1 ? Xh[(r1 * K + kA + 8) >> 1] : 0u;
        } else {
            float2 f0 = p0 ? *(const float2*)&Xf[r0 * K + kA]     : make_float2(0.f, 0.f);
            float2 f1 = p1 ? *(const float2*)&Xf[r1 * K + kA]     : make_float2(0.f, 0.f);
            float2 f2 = p0 ? *(const float2*)&Xf[r0 * K + kA + 8] : make_float2(0.f, 0.f);
            float2 f3 = p1 ? *(const float2*)&Xf[r1 * K + kA + 8] : make_float2(0.f, 0.f);
            a[0] = packh2(f0.x, f0.y);
            a[1] = packh2(f1.x, f1.y);
            a[2] = packh2(f2.x, f2.y);
            a[3] = packh2(f3.x, f3.y);
        }
        const uint2* bp = Bp + ks * 512 + lane;
#pragma unroll
        for (int tp = 0; tp < 16; tp++) {
            uint2 b = bp[tp * 32];
            mma16(acc[tp], a, b.x, b.y);
        }
    }

#pragma unroll
    for (int n = 0; n < 16; n++) {
        int c = n * 8 + 2 * t;
        if (p0) hhOut[(r0 * 128 + c) >> 1] = packh2(acc[n][0], acc[n][1]);
        if (p1) hhOut[(r1 * 128 + c) >> 1] = packh2(acc[n][2], acc[n][3]);
    }

    float sa[2][2] = {};
    float sd_[2][2] = {};
#pragma unroll
    for (int n = 0; n < 16; n++) {
        int c = n * 8 + 2 * t;
        float v0 = asv[c], v1 = asv[c + 1];
        float u0 = adv[c], u1 = adv[c + 1];
        int hh = n >> 3;
        sa[0][hh] += acc[n][0] * v0 + acc[n][1] * v1;
        sa[1][hh] += acc[n][2] * v0 + acc[n][3] * v1;
        sd_[0][hh] += acc[n][0] * u0 + acc[n][1] * u1;
        sd_[1][hh] += acc[n][2] * u0 + acc[n][3] * u1;
    }
#pragma unroll
    for (int rh = 0; rh < 2; rh++)
#pragma unroll
        for (int hh = 0; hh < 2; hh++) {
            sa[rh][hh] += __shfl_xor_sync(~0u, sa[rh][hh], 1);
            sa[rh][hh] += __shfl_xor_sync(~0u, sa[rh][hh], 2);
            sd_[rh][hh] += __shfl_xor_sync(~0u, sd_[rh][hh], 1);
            sd_[rh][hh] += __shfl_xor_sync(~0u, sd_[rh][hh], 2);
        }
    if (t == 0) {
        if (p0) {
            asrcOut[r0 * 2] = sa[0][0]; asrcOut[r0 * 2 + 1] = sa[0][1];
            adstOut[r0 * 2] = sd_[0][0]; adstOut[r0 * 2 + 1] = sd_[0][1];
        }
        if (p1) {
            asrcOut[r1 * 2] = sa[1][0]; asrcOut[r1 * 2 + 1] = sa[1][1];
            adstOut[r1 * 2] = sd_[1][0]; adstOut[r1 * 2 + 1] = sd_[1][1];
        }
    }
}

// =================== aggregate over node range [n0, n1) ===================
// R12 structure (best measured): smem-staged exp values, unnormalized accumulate.
// Deltas: 4-warp CTAs (tail imbalance), pre-scaled src offsets in smem.
template <bool FC, bool RESET>
__global__ void __launch_bounds__(128) aggregate_kernel(
                                 const uint* __restrict__ hh,
                                 const float* __restrict__ asrc,
                                 const float* __restrict__ adst,
                                 const float* __restrict__ bias,
                                 const float* __restrict__ fcW,
                                 const float* __restrict__ fcb,
                                 float* __restrict__ out,
                                 int n0, int n1) {
    __shared__ int   s_src[4][32];   // pre-scaled: src << 6 (uint index of h row)
    __shared__ float s_p[4][64];     // [w][2*j + head]
    int tid = threadIdx.x;
    int wiw = tid >> 5;
    int warp = n0 + ((blockIdx.x * blockDim.x + tid) >> 5);
    int lane = tid & 31;
    if (warp >= n1) return;
    int base = warp << 7;
    int cnt = min(g_cnt[warp], CAP);
    float2 ad = *(const float2*)&adst[warp * 2];
    bool lo = (lane < 16);

    // self-loop logit
    float2 aself = *(const float2*)&asrc[warp * 2];
    float se0 = aself.x + ad.x; se0 = se0 > 0.f ? se0 : NEG_SLOPE * se0;
    float se1 = aself.y + ad.y; se1 = se1 > 0.f ? se1 : NEG_SLOPE * se1;
    se0 = __expf(fminf(se0, 60.f));
    se1 = __expf(fminf(se1, 60.f));

    // pass 1: edge logits + exp + sum; first 32 edges staged to smem
    float s0 = (lane == 0) ? se0 : 0.f;
    float s1 = (lane == 0) ? se1 : 0.f;
    if (lane < cnt) {
        int s = g_ell[base + lane];
        float2 as = *(const float2*)&asrc[s * 2];
        float e0 = as.x + ad.x; e0 = e0 > 0.f ? e0 : NEG_SLOPE * e0;
        float e1 = as.y + ad.y; e1 = e1 > 0.f ? e1 : NEG_SLOPE * e1;
        float fp0 = __expf(fminf(e0, 60.f));
        float fp1 = __expf(fminf(e1, 60.f));
        s_src[wiw][lane] = s << 6;
        s_p[wiw][2 * lane]     = fp0;
        s_p[wiw][2 * lane + 1] = fp1;
        s0 += fp0; s1 += fp1;
        for (int j = lane + 32; j < cnt; j += 32) {
            int s2 = g_ell[base + j];
            float2 a2 = *(const float2*)&asrc[s2 * 2];
            float q0 = a2.x + ad.x; q0 = q0 > 0.f ? q0 : NEG_SLOPE * q0;
            float q1 = a2.y + ad.y; q1 = q1 > 0.f ? q1 : NEG_SLOPE * q1;
            s0 += __expf(fminf(q0, 60.f));
            s1 += __expf(fminf(q1, 60.f));
        }
    }
    __syncwarp();
#pragma unroll
    for (int o = 16; o > 0; o >>= 1) {
        s0 += __shfl_xor_sync(~0u, s0, o);
        s1 += __shfl_xor_sync(~0u, s1, o);
    }
    float inv = lo ? 1.f / (s0 + 1e-16f) : 1.f / (s1 + 1e-16f);

    // pass 2: UNNORMALIZED weighted fp16 gather; self term first
    u64 acc01, acc23;
    const uint* hbase = hh + lane * 2;
    {
        float a = lo ? se0 : se1;
        uint2 hu = *(const uint2*)&hbase[warp * 64];
        float2 f0 = __half22float2(*(__half2*)&hu.x);
        float2 f1 = __half22float2(*(__half2*)&hu.y);
        acc01 = packf2(a * f0.x, a * f0.y);
        acc23 = packf2(a * f1.x, a * f1.y);
    }
    const float* pb = &s_p[wiw][lo ? 0 : 1];
    int cn = min(32, cnt);
#pragma unroll 4
    for (int j = 0; j < cn; j++) {
        int   soff = s_src[wiw][j];
        float a = pb[2 * j];
        u64 aa = packf2(a, a);
        uint2 hu = *(const uint2*)&hbase[soff];
        float2 f0 = __half22float2(*(__half2*)&hu.x);
        float2 f1 = __half22float2(*(__half2*)&hu.y);
        fma_f32x2(acc01, packf2(f0.x, f0.y), aa);
        fma_f32x2(acc23, packf2(f1.x, f1.y), aa);
    }
    float2 a01 = unpackf2(acc01), a23 = unpackf2(acc23);
    float4 acc = make_float4(a01.x, a01.y, a23.x, a23.y);

    // cold path: degree > 32 — recompute exp, accumulate unnormalized
    for (int jb = 32; jb < cnt; jb += 32) {
        int idx = jb + lane;
        int   ls = 0;
        float lp0 = 0.f, lp1 = 0.f;
        if (idx < cnt) {
            ls = g_ell[base + idx];
            float2 a2 = *(const float2*)&asrc[ls * 2];
            float q0 = a2.x + ad.x; q0 = q0 > 0.f ? q0 : NEG_SLOPE * q0;
            float q1 = a2.y + ad.y; q1 = q1 > 0.f ? q1 : NEG_SLOPE * q1;
            lp0 = __expf(fminf(q0, 60.f));
            lp1 = __expf(fminf(q1, 60.f));
        }
        int n = min(32, cnt - jb);
        for (int j = 0; j < n; j++) {
            int   s  = __shfl_sync(~0u, ls, j);
            float q0 = __shfl_sync(~0u, lp0, j);
            float q1 = __shfl_sync(~0u, lp1, j);
            float a = lo ? q0 : q1;
            uint2 hu = *(const uint2*)&hbase[s * 64];
            float2 f0 = __half22float2(*(__half2*)&hu.x);
            float2 f1 = __half22float2(*(__half2*)&hu.y);
            acc.x += a * f0.x; acc.y += a * f0.y; acc.z += a * f1.x; acc.w += a * f1.y;
        }
    }

    // normalize, then head mean
    acc.x *= inv; acc.y *= inv; acc.z *= inv; acc.w *= inv;
    float4 o4;
    o4.x = (acc.x + __shfl_xor_sync(~0u, acc.x, 16)) * 0.5f;
    o4.y = (acc.y + __shfl_xor_sync(~0u, acc.y, 16)) * 0.5f;
    o4.z = (acc.z + __shfl_xor_sync(~0u, acc.z, 16)) * 0.5f;
    o4.w = (acc.w + __shfl_xor_sync(~0u, acc.w, 16)) * 0.5f;

    if (RESET) {
        if (lane == 0) g_cnt[warp] = 0;   // restore countdown invariant for next replay
    }

    if (!FC) {
        if (lane < 16) {
            float4 b4 = *(const float4*)&bias[lane * 4];
            o4.x = fmaxf(o4.x + b4.x, 0.f);
            o4.y = fmaxf(o4.y + b4.y, 0.f);
            o4.z = fmaxf(o4.z + b4.z, 0.f);
            o4.w = fmaxf(o4.w + b4.w, 0.f);
            uint2 p;
            p.x = packh2(o4.x, o4.y);
            p.y = packh2(o4.z, o4.w);
            *(uint2*)&((uint*)out)[warp * 32 + lane * 2] = p;
        }
    } else {
        float p = 0.f;
        if (lane < 16) {
            float4 b4 = *(const float4*)&bias[lane * 4];
            float4 w4 = *(const float4*)&fcW[lane * 4];
            p  = fmaxf(o4.x + b4.x, 0.f) * w4.x;
            p += fmaxf(o4.y + b4.y, 0.f) * w4.y;
            p += fmaxf(o4.z + b4.z, 0.f) * w4.z;
            p += fmaxf(o4.w + b4.w, 0.f) * w4.w;
        }
#pragma unroll
        for (int o = 8; o > 0; o >>= 1) p += __shfl_xor_sync(~0u, p, o);
        if (lane == 0) out[warp] = p + fcb[0];
    }
}

// =================== host orchestration ===================
extern "C" void kernel_launch(void* const* d_in, const int* in_sizes, int n_in,
                              void* d_out, int out_size) {
    const float* x        = (const float*)d_in[0];
    const int*   ei       = (const int*)  d_in[1];
    const float* W1       = (const float*)d_in[2];
    const float* att_src1 = (const float*)d_in[3];
    const float* att_dst1 = (const float*)d_in[4];
    const float* b1       = (const float*)d_in[5];
    const float* W2       = (const float*)d_in[6];
    const float* att_src2 = (const float*)d_in[7];
    const float* att_dst2 = (const float*)d_in[8];
    const float* b2       = (const float*)d_in[9];
    const float* fc_W     = (const float*)d_in[10];
    const float* fc_b     = (const float*)d_in[11];
    float* out = (float*)d_out;

    uint *x2p, *hh1, *hh2;
    float *as1, *ad1, *as2, *ad2;
    uint2 *bp1, *bp2;
    cudaGetSymbolAddress((void**)&x2p, g_x2h);
    cudaGetSymbolAddress((void**)&hh1, g_hh1);
    cudaGetSymbolAddress((void**)&hh2, g_hh2);
    cudaGetSymbolAddress((void**)&as1, g_asrc1);
    cudaGetSymbolAddress((void**)&ad1, g_adst1);
    cudaGetSymbolAddress((void**)&as2, g_asrc2);
    cudaGetSymbolAddress((void**)&ad2, g_adst2);
    cudaGetSymbolAddress((void**)&bp1, g_Bp1);
    cudaGetSymbolAddress((void**)&bp2, g_Bp2);

    static cudaStream_t s2 = nullptr;
    static cudaEvent_t evFork = nullptr, evF = nullptr, evG = nullptr, evJ = nullptr;
    if (s2 == nullptr) {
        cudaStreamCreateWithFlags(&s2, cudaStreamNonBlocking);
        cudaEventCreateWithFlags(&evFork, cudaEventDisableTiming);
        cudaEventCreateWithFlags(&evF, cudaEventDisableTiming);
        cudaEventCreateWithFlags(&evG, cudaEventDisableTiming);
        cudaEventCreateWithFlags(&evJ, cudaEventDisableTiming);
    }

    cudaEventRecord(evFork, 0);
    cudaStreamWaitEvent(s2, evFork, 0);

    // main: ELL build (cnt starts at 0 by invariant)
    fill_kernel<<<(Ee / 4 + 255) / 256, 256>>>(ei);
    cudaEventRecord(evF, 0);

    // s2: merged weight prep + full layer-1 GEMM (writes layer-1 buffers)
    bprep_all_kernel<<<(12 * 512 + 255) / 256, 256, 0, s2>>>(W1, W2);
    gemm_att_kernel<128, false><<<(Nn + 63) / 64, 128, 0, s2>>>(
        x, bp1, att_src1, att_dst1, hh1, as1, ad1, 0, Nn);
    cudaEventRecord(evG, s2);

    // pipelined halves: layer-2 GEMM writes separate buffers -> race-free
    cudaStreamWaitEvent(0, evG, 0);      // main agg1a needs gemm1 (s2)
    cudaStreamWaitEvent(s2, evF, 0);     // s2 agg1b needs ELL (main)

    aggregate_kernel<false, false><<<(H1 * 32 + 127) / 128, 128>>>(
        hh1, as1, ad1, b1, nullptr, nullptr, (float*)x2p, 0, H1);
    gemm_att_kernel<64, true><<<(H1 + 63) / 64, 128>>>(
        x2p, bp2, att_src2, att_dst2, hh2, as2, ad2, 0, H1);

    aggregate_kernel<false, false><<<((Nn - H1) * 32 + 127) / 128, 128, 0, s2>>>(
        hh1, as1, ad1, b1, nullptr, nullptr, (float*)x2p, H1, Nn);
    gemm_att_kernel<64, true><<<(Nn - H1 + 63) / 64, 128, 0, s2>>>(
        x2p, bp2, att_src2, att_dst2, hh2, as2, ad2, H1, Nn);
    cudaEventRecord(evJ, s2);

    // final aggregate (needs both halves of layer-2 buffers)
    cudaStreamWaitEvent(0, evJ, 0);
    aggregate_kernel<true, true><<<(Nn * 32 + 127) / 128, 128>>>(
        hh2, as2, ad2, b2, fc_W, fc_b, out, 0, Nn);
}